// round 11
// baseline (speedup 1.0000x reference)
#include <cuda_runtime.h>
#include <cuda_bf16.h>
#include <math.h>
#include <stdint.h>

#define B_  32
#define T_  20
#define C_  512
#define P_  196
#define H_  1024
#define NC_ 101
#define NBLK 148
#define NTHR 512
#define NWRP 16
#define MT  32            // blocks doing MMA (4096 gate-rows / 128)
#define KCH 128           // k elements per chunk

// SMEM byte layout: A tiles [128 m][128 k] bf16 @ stride 272 B, B tiles [32 n][128 k]
#define ASTR_B 272
#define AHI_B 0                     // 128*272 = 34816
#define ALO_B 34816
#define BHI_B 69632                 // 32*272 = 8704
#define BLO_B 78336
#define TBUF_B 87040                // per buffer
#define SMEM_BYTES (2 * TBUF_B)     // 174080

// ---------------- device scratch ----------------
__device__ float g_sA2pre[T_ * B_ * P_];
__device__ float g_tC2pre[T_ * B_ * P_];
__device__ float g_sc[B_ * P_];
__device__ float g_betaH[B_];
__device__ float g_h2n[B_ * H_];          // [b][h] fp32 (scores)
__device__ float g_h2hist[T_ * H_ * B_];  // [t][h][b]
__device__ float g_c1[H_ * B_];           // [h][b]
__device__ float g_c2[H_ * B_];
__device__ float g_beta[T_ * B_];
__device__ float g_betasT[B_ * T_];
__device__ float g_hbarN[B_ * H_];
__device__ unsigned g_cnt2[32 * 32];
__device__ volatile unsigned g_bar_gen;

// bf16 hi/lo activations [b][k]
__device__ __nv_bfloat16 g_Yhi[B_ * C_], g_Ylo[B_ * C_];
__device__ __nv_bfloat16 g_h1hi[B_ * H_], g_h1lo[B_ * H_];
__device__ __nv_bfloat16 g_h2hi[B_ * H_], g_h2lo[B_ * H_];

// repacked (row-permuted, K-major) weights, hi/lo bf16
__device__ __nv_bfloat16 g_W1hi[4096 * 1536], g_W1lo[4096 * 1536];
__device__ __nv_bfloat16 g_W2hi[4096 * 2048], g_W2lo[4096 * 2048];

__device__ __forceinline__ float sigm(float x) { return 1.0f / (1.0f + __expf(-x)); }
__device__ __forceinline__ float ftanh(float x) { return 1.0f - 2.0f / (__expf(2.0f * x) + 1.0f); }
__device__ __forceinline__ float d4(float4 a, float4 b) {
    return a.x * b.x + a.y * b.y + a.z * b.z + a.w * b.w;
}

__device__ __forceinline__ void cp16(void* dst, const void* src) {
    unsigned u = (unsigned)__cvta_generic_to_shared(dst);
    asm volatile("cp.async.cg.shared.global [%0], [%1], 16;" :: "r"(u), "l"(src));
}
__device__ __forceinline__ void cp_commit() { asm volatile("cp.async.commit_group;" ::: "memory"); }
__device__ __forceinline__ void cp_wait1()  { asm volatile("cp.async.wait_group 1;" ::: "memory"); }
__device__ __forceinline__ void cp_wait0()  { asm volatile("cp.async.wait_group 0;" ::: "memory"); }

__device__ __forceinline__ uint32_t smem_u32(const void* p) {
    return (uint32_t)__cvta_generic_to_shared(p);
}

// ldmatrix x4 (b16)
__device__ __forceinline__ void ldsm4(uint32_t* r, uint32_t addr) {
    asm volatile("ldmatrix.sync.aligned.m8n8.x4.shared.b16 {%0,%1,%2,%3}, [%4];"
                 : "=r"(r[0]), "=r"(r[1]), "=r"(r[2]), "=r"(r[3]) : "r"(addr));
}
// HMMA m16n8k16 bf16 -> f32 accumulate
__device__ __forceinline__ void mma16816(float* d, const uint32_t* a, const uint32_t* b) {
    asm volatile(
        "mma.sync.aligned.m16n8k16.row.col.f32.bf16.bf16.f32 "
        "{%0,%1,%2,%3}, {%4,%5,%6,%7}, {%8,%9}, {%0,%1,%2,%3};"
        : "+f"(d[0]), "+f"(d[1]), "+f"(d[2]), "+f"(d[3])
        : "r"(a[0]), "r"(a[1]), "r"(a[2]), "r"(a[3]), "r"(b[0]), "r"(b[1]));
}

// distributed grid barrier
__device__ __forceinline__ void grid_sync(unsigned& barI, unsigned gen0) {
    barI++;
    __syncthreads();
    const int tid = threadIdx.x, bid = blockIdx.x;
    if (tid == 0) { __threadfence(); atomicAdd(&g_cnt2[(bid & 31) * 32], 1u); }
    if (bid == 0 && tid < 32) {
        unsigned nj = (tid < 20) ? 5u : 4u;
        volatile unsigned* c = &g_cnt2[tid * 32];
        while (*c < nj) __nanosleep(32);
        atomicSub(&g_cnt2[tid * 32], nj);
        __syncwarp(0xffffffffu);
        if (tid == 0) { __threadfence(); g_bar_gen = gen0 + barI; }
    } else if (tid == 0) {
        while ((unsigned)(g_bar_gen - gen0) < barI) __nanosleep(32);
    }
    __threadfence();
    __syncthreads();
}

// ---------------- LSTM phase: HMMA bf16-split GEMM + fused cell ----------------
// blocks 0..31; block m: 128 permuted gate-rows = 4 gates x 32 units (u = m*32..m*32+31)
// warp w: m-strip (w&7)*16, n-half (w>>3)*16. 3-term hi/lo split, fp32 accum.
template <int MODE>
__device__ void lstm_mma(int t, const __nv_bfloat16* __restrict__ Whi,
                         const __nv_bfloat16* __restrict__ Wlo,
                         const float* __restrict__ bih, const float* __restrict__ bhh,
                         float* dsm, uint32_t smem_base) {
    constexpr int K = (MODE == 0) ? 1536 : 2048;
    constexpr int K1 = (MODE == 0) ? 512 : 1024;
    constexpr int NCH = K / KCH;
    const int bid = blockIdx.x, tid = threadIdx.x;
    if (bid >= MT) return;
    const int m = bid;

    const __nv_bfloat16* X1hi = (MODE == 0) ? g_Yhi : g_h1hi;
    const __nv_bfloat16* X1lo = (MODE == 0) ? g_Ylo : g_h1lo;
    const __nv_bfloat16* X2hi = (MODE == 0) ? g_h1hi : g_h2hi;
    const __nv_bfloat16* X2lo = (MODE == 0) ? g_h1lo : g_h2lo;
    const int X1STR = (MODE == 0) ? 512 : 1024;

    char* smem_c = (char*)dsm;

    auto load_chunk = [&](int c) {
        char* basep = smem_c + (c & 1) * TBUF_B;
        const int kc = c * KCH;
        // A: 2048 granules of 16B (128 rows x 16)
#pragma unroll
        for (int i = 0; i < 4; i++) {
            int g = tid + 512 * i;
            int row = g >> 4, gi = g & 15;
            size_t soff = (size_t)(m * 128 + row) * K + kc + gi * 8;
            cp16(basep + AHI_B + row * ASTR_B + gi * 16, Whi + soff);
            cp16(basep + ALO_B + row * ASTR_B + gi * 16, Wlo + soff);
        }
        // B: 512 granules (32 rows x 16)
        {
            int row = tid >> 4, gi = tid & 15;
            int k = kc + gi * 8;
            const __nv_bfloat16 *shi, *slo;
            if (k < K1) { shi = X1hi + row * X1STR + k; slo = X1lo + row * X1STR + k; }
            else        { shi = X2hi + row * 1024 + (k - K1); slo = X2lo + row * 1024 + (k - K1); }
            cp16(basep + BHI_B + row * ASTR_B + gi * 16, shi);
            cp16(basep + BLO_B + row * ASTR_B + gi * 16, slo);
        }
    };

    const int w = tid >> 5, lane = tid & 31;
    const int m0 = (w & 7) * 16, n0 = (w >> 3) * 16;
    // ldmatrix per-lane address components
    const int mi = lane >> 3, rr = lane & 7;
    const int a_m = m0 + (mi & 1) * 8 + rr, a_k = (mi >> 1) * 8;       // A mats: m0-7/k0, m8-15/k0, m0-7/k8, m8-15/k8
    const int b_n = n0 + (mi >> 1) * 8 + rr, b_k = (mi & 1) * 8;       // B mats: t0/k0, t0/k8, t1/k0, t1/k8

    float acc[2][4] = {{0.f, 0.f, 0.f, 0.f}, {0.f, 0.f, 0.f, 0.f}};

    load_chunk(0); cp_commit();
    load_chunk(1); cp_commit();

    for (int c = 0; c < NCH; c++) {
        if (c + 1 < NCH) cp_wait1(); else cp_wait0();
        __syncthreads();

        uint32_t tb = smem_base + (c & 1) * TBUF_B;
        uint32_t aHi = tb + AHI_B + a_m * ASTR_B + a_k * 2;
        uint32_t aLo = tb + ALO_B + a_m * ASTR_B + a_k * 2;
        uint32_t bHi = tb + BHI_B + b_n * ASTR_B + b_k * 2;
        uint32_t bLo = tb + BLO_B + b_n * ASTR_B + b_k * 2;
#pragma unroll
        for (int kk = 0; kk < 8; kk++) {
            uint32_t ah[4], al[4], bh[4], bl[4];
            ldsm4(ah, aHi + kk * 32);
            ldsm4(al, aLo + kk * 32);
            ldsm4(bh, bHi + kk * 32);
            ldsm4(bl, bLo + kk * 32);
            mma16816(acc[0], ah, bh + 0);
            mma16816(acc[1], ah, bh + 2);
            mma16816(acc[0], ah, bl + 0);
            mma16816(acc[1], ah, bl + 2);
            mma16816(acc[0], al, bh + 0);
            mma16816(acc[1], al, bh + 2);
        }
        __syncthreads();
        if (c + 2 < NCH) { load_chunk(c + 2); cp_commit(); }
    }

    // epilogue: fragments -> smem [128][33] -> fused cell update
    float* sG = dsm;
    {
        int gm = lane >> 2, qc = (lane & 3) * 2;
        int r1 = m0 + gm, r2 = r1 + 8;
#pragma unroll
        for (int tt = 0; tt < 2; tt++) {
            int cc = n0 + tt * 8 + qc;
            sG[r1 * 33 + cc]     = acc[tt][0];
            sG[r1 * 33 + cc + 1] = acc[tt][1];
            sG[r2 * 33 + cc]     = acc[tt][2];
            sG[r2 * 33 + cc + 1] = acc[tt][3];
        }
    }
    __syncthreads();
    for (int idx = tid; idx < 1024; idx += NTHR) {
        int u = idx >> 5, b = idx & 31;
        int ug = m * 32 + u;
        float gi = sG[(0 * 32 + u) * 33 + b] + bih[ug] + bhh[ug];
        float gf = sG[(1 * 32 + u) * 33 + b] + bih[1024 + ug] + bhh[1024 + ug];
        float gg = sG[(2 * 32 + u) * 33 + b] + bih[2048 + ug] + bhh[2048 + ug];
        float go = sG[(3 * 32 + u) * 33 + b] + bih[3072 + ug] + bhh[3072 + ug];
        float i_ = sigm(gi), f_ = sigm(gf), gv = ftanh(gg), o_ = sigm(go);
        float* cS = (MODE == 0) ? g_c1 : g_c2;
        float cn = f_ * cS[ug * 32 + b] + i_ * gv;
        float hn = o_ * ftanh(cn);
        cS[ug * 32 + b] = cn;
        __nv_bfloat16 hhi = __float2bfloat16(hn);
        __nv_bfloat16 hlo = __float2bfloat16(hn - __bfloat162float(hhi));
        if (MODE == 0) {
            g_h1hi[b * 1024 + ug] = hhi;
            g_h1lo[b * 1024 + ug] = hlo;
        } else {
            g_h2hi[b * 1024 + ug] = hhi;
            g_h2lo[b * 1024 + ug] = hlo;
            g_h2n[b * 1024 + ug] = hn;
            g_h2hist[(size_t)t * H_ * B_ + ug * B_ + b] = hn;
        }
    }
    __syncthreads();
}

// ---------------- the single persistent kernel ----------------
__global__ void __launch_bounds__(NTHR, 1)
stdec_kernel(const float* __restrict__ videos,
             const float* __restrict__ h1in, const float* __restrict__ c1in,
             const float* __restrict__ h2in, const float* __restrict__ c2in,
             const float* __restrict__ spatialBias, const float* __restrict__ temporalBias,
             const float* __restrict__ W_h2p, const float* __restrict__ b_h2p,
             const float* __restrict__ W_sC21, const float* __restrict__ b_sC21,
             const float* __restrict__ W_h21, const float* __restrict__ b_h21,
             const float* __restrict__ W_tC21, const float* __restrict__ b_tC21,
             const float* __restrict__ Wih1, const float* __restrict__ Whh1,
             const float* __restrict__ bih1, const float* __restrict__ bhh1,
             const float* __restrict__ Wih2, const float* __restrict__ Whh2,
             const float* __restrict__ bih2, const float* __restrict__ bhh2,
             const float* __restrict__ W_fc, const float* __restrict__ b_fc,
             float* __restrict__ logits_out, float* __restrict__ alphas_out,
             float* __restrict__ betasT_out) {
    extern __shared__ __align__(1024) float dsm[];
    const int bid = blockIdx.x, tid = threadIdx.x;
    const int lane = tid & 31, wid = tid >> 5;
    const int gw = bid * NWRP + wid;

    unsigned barI = 0;
    unsigned gen0 = g_bar_gen;
    uint32_t smem_base = smem_u32(dsm);

    // ---- init states ----
    for (int idx = bid * NTHR + tid; idx < B_ * H_; idx += NBLK * NTHR) {
        int b = idx >> 10, h = idx & 1023;
        float v1 = h1in[h], v2 = h2in[h];
        __nv_bfloat16 t1 = __float2bfloat16(v1);
        g_h1hi[idx] = t1; g_h1lo[idx] = __float2bfloat16(v1 - __bfloat162float(t1));
        __nv_bfloat16 t2 = __float2bfloat16(v2);
        g_h2hi[idx] = t2; g_h2lo[idx] = __float2bfloat16(v2 - __bfloat162float(t2));
        g_h2n[idx] = v2;
        g_c1[h * 32 + b] = c1in[h];
        g_c2[h * 32 + b] = c2in[h];
    }

    // ---- weight repack: permuted rows, K-major, hi/lo bf16 (once per launch) ----
    {
        const size_t N1 = (size_t)4096 * 1536, N2 = (size_t)4096 * 2048;
        for (size_t idx = (size_t)(bid * NTHR + tid); idx < N1 + N2; idx += (size_t)NBLK * NTHR) {
            if (idx < N1) {
                int R = (int)(idx / 1536), k = (int)(idx % 1536);
                int r = R & 127, mm = R >> 7;
                int q = r >> 5, u = (mm << 5) + (r & 31);
                int orig = q * 1024 + u;
                float w = (k < 512) ? Wih1[(size_t)orig * 512 + k]
                                    : Whh1[(size_t)orig * 1024 + (k - 512)];
                __nv_bfloat16 hi = __float2bfloat16(w);
                g_W1hi[idx] = hi;
                g_W1lo[idx] = __float2bfloat16(w - __bfloat162float(hi));
            } else {
                size_t j = idx - N1;
                int R = (int)(j / 2048), k = (int)(j % 2048);
                int r = R & 127, mm = R >> 7;
                int q = r >> 5, u = (mm << 5) + (r & 31);
                int orig = q * 1024 + u;
                float w = (k < 1024) ? Wih2[(size_t)orig * 1024 + k]
                                     : Whh2[(size_t)orig * 1024 + (k - 1024)];
                __nv_bfloat16 hi = __float2bfloat16(w);
                g_W2hi[j] = hi;
                g_W2lo[j] = __float2bfloat16(w - __bfloat162float(hi));
            }
        }
    }

    // ---- precompute sA2pre / tC2pre (2 tasks per block) ----
    {
        float* ws = dsm;
        float* wt = dsm + C_;
        for (int i = tid; i < C_; i += NTHR) { ws[i] = W_sC21[i]; wt[i] = W_tC21[i]; }
        __syncthreads();
        float bs0 = b_sC21[0];
        int half = tid >> 8, p = tid & 255;
        for (int task = bid * 2 + half; task < B_ * T_; task += NBLK * 2) {
            int b = task / T_, t = task % T_;
            if (p < P_) {
                const float* vp = videos + ((size_t)(b * T_ + t) * C_) * P_ + p;
                float accs = 0.f, acct = 0.f;
#pragma unroll 8
                for (int c = 0; c < C_; c++) {
                    float v = vp[(size_t)c * P_];
                    accs += v * ws[c];
                    acct += v * wt[c];
                }
                int o = (t * B_ + b) * P_ + p;
                g_sA2pre[o] = accs + bs0 + spatialBias[p];
                g_tC2pre[o] = acct;
            }
        }
        __syncthreads();
    }
    grid_sync(barI, gen0);

    // ---- recurrence: 4 phases / 4 barriers per step ----
    for (int t = 0; t < T_; t++) {
        // phase 1: scores, warp per (b,p) dot; p==196 -> betaH
        for (int task = gw; task < B_ * 197; task += NBLK * NWRP) {
            int b = task / 197, p = task % 197;
            const float4* xr = (const float4*)(g_h2n + b * H_);
            const float4* wr = (const float4*)((p < P_) ? (W_h2p + (size_t)p * H_) : W_h21);
            float acc = 0.f;
#pragma unroll
            for (int j = 0; j < 8; j++) acc += d4(wr[lane + 32 * j], xr[lane + 32 * j]);
            for (int o = 16; o; o >>= 1) acc += __shfl_xor_sync(~0u, acc, o);
            if (lane == 0) {
                if (p < P_)
                    g_sc[b * P_ + p] = acc + b_h2p[p] + g_sA2pre[(t * B_ + b) * P_ + p];
                else
                    g_betaH[b] = acc;
            }
        }
        grid_sync(barI, gen0);

        // phase 2: softmax + alpha/beta out + Y (blocks 0..127)
        if (bid < 128) {
            float* sred = dsm;
            float* s_alpha = dsm + 16;
            int b = bid >> 2, chunk = bid & 3, c0 = chunk * 128;

            float v = (tid < P_) ? g_sc[b * P_ + tid] : -1e30f;
            float m = v;
            for (int o = 16; o; o >>= 1) m = fmaxf(m, __shfl_xor_sync(~0u, m, o));
            if (lane == 0) sred[wid] = m;
            __syncthreads();
            float mAll = sred[0];
#pragma unroll
            for (int i = 1; i < NWRP; i++) mAll = fmaxf(mAll, sred[i]);
            float e = (tid < P_) ? __expf(v - mAll) : 0.f;
            float s = e;
            for (int o = 16; o; o >>= 1) s += __shfl_xor_sync(~0u, s, o);
            __syncthreads();
            if (lane == 0) sred[wid] = s;
            __syncthreads();
            float sAll = sred[0];
#pragma unroll
            for (int i = 1; i < NWRP; i++) sAll += sred[i];
            float a = e / sAll;
            __syncthreads();
            if (tid < P_) {
                s_alpha[tid] = a;
                if (chunk == 0) alphas_out[((size_t)t * B_ + b) * P_ + tid] = a;
            }
            __syncthreads();

            if (chunk == 0) {
                float acc = (tid < P_) ? a * g_tC2pre[(t * B_ + b) * P_ + tid] : 0.f;
                for (int o = 16; o; o >>= 1) acc += __shfl_xor_sync(~0u, acc, o);
                if (lane == 0) sred[wid] = acc;
                __syncthreads();
                if (tid == 0) {
                    float sum = 0.f;
#pragma unroll
                    for (int i = 0; i < NWRP; i++) sum += sred[i];
                    g_beta[t * B_ + b] = sum + g_betaH[b] + b_h21[0] + b_tC21[0] + temporalBias[0];
                }
            }

            // Y -> bf16 hi/lo [b][c]
            for (int c = wid; c < 128; c += NWRP) {
                int cg = c0 + c;
                const float* vp = videos + (((size_t)b * T_ + t) * C_ + cg) * P_;
                float acc = 0.f;
                for (int p = lane; p < P_; p += 32) acc += s_alpha[p] * vp[p];
                for (int o = 16; o; o >>= 1) acc += __shfl_xor_sync(~0u, acc, o);
                if (lane == 0) {
                    __nv_bfloat16 hy = __float2bfloat16(acc);
                    g_Yhi[b * C_ + cg] = hy;
                    g_Ylo[b * C_ + cg] = __float2bfloat16(acc - __bfloat162float(hy));
                }
            }
        }
        grid_sync(barI, gen0);

        lstm_mma<0>(t, g_W1hi, g_W1lo, bih1, bhh1, dsm, smem_base);
        grid_sync(barI, gen0);
        lstm_mma<1>(t, g_W2hi, g_W2lo, bih2, bhh2, dsm, smem_base);
        grid_sync(barI, gen0);
    }

    // ---- betas softmax over time ----
    if (bid == 0 && tid < B_) {
        int b = tid;
        float v[T_];
        float m = -1e30f;
#pragma unroll
        for (int t = 0; t < T_; t++) { v[t] = g_beta[t * B_ + b]; m = fmaxf(m, v[t]); }
        float s = 0.f;
#pragma unroll
        for (int t = 0; t < T_; t++) { v[t] = __expf(v[t] - m); s += v[t]; }
        float inv = 1.f / s;
#pragma unroll
        for (int t = 0; t < T_; t++) {
            float bt = v[t] * inv;
            g_betasT[b * T_ + t] = bt;
            betasT_out[b * T_ + t] = bt;
        }
    }
    grid_sync(barI, gen0);

    // ---- hbar[b][h] = sum_t betasT[b][t] * h2hist[t][h][b] ----
    for (int idx = bid * NTHR + tid; idx < H_ * B_; idx += NBLK * NTHR) {
        int h = idx >> 5, b = idx & 31;
        float acc = 0.f;
#pragma unroll
        for (int t = 0; t < T_; t++)
            acc += g_betasT[b * T_ + t] * g_h2hist[(size_t)t * H_ * B_ + h * B_ + b];
        g_hbarN[b * H_ + h] = acc;
    }
    grid_sync(barI, gen0);

    // ---- logits ----
    for (int task = gw; task < NC_ * B_; task += NBLK * NWRP) {
        int nc = task / B_, b = task % B_;
        const float4* wr = (const float4*)(W_fc + (size_t)nc * H_);
        const float4* xr = (const float4*)(g_hbarN + (size_t)b * H_);
        float acc = 0.f;
#pragma unroll
        for (int j = 0; j < 8; j++) acc += d4(wr[lane + 32 * j], xr[lane + 32 * j]);
        for (int o = 16; o; o >>= 1) acc += __shfl_xor_sync(~0u, acc, o);
        if (lane == 0) logits_out[b * NC_ + nc] = acc + b_fc[nc];
    }
}

// ---------------- launch ----------------
extern "C" void kernel_launch(void* const* d_in, const int* in_sizes, int n_in,
                              void* d_out, int out_size) {
    const float* videos       = (const float*)d_in[0];
    const float* h1           = (const float*)d_in[1];
    const float* c1           = (const float*)d_in[2];
    const float* h2           = (const float*)d_in[3];
    const float* c2           = (const float*)d_in[4];
    const float* spatialBias  = (const float*)d_in[5];
    const float* temporalBias = (const float*)d_in[6];
    const float* W_h2p        = (const float*)d_in[7];
    const float* b_h2p        = (const float*)d_in[8];
    const float* W_sC21       = (const float*)d_in[9];
    const float* b_sC21       = (const float*)d_in[10];
    const float* W_h21        = (const float*)d_in[11];
    const float* b_h21        = (const float*)d_in[12];
    const float* W_tC21       = (const float*)d_in[13];
    const float* b_tC21       = (const float*)d_in[14];
    const float* Wih1         = (const float*)d_in[15];
    const float* Whh1         = (const float*)d_in[16];
    const float* bih1         = (const float*)d_in[17];
    const float* bhh1         = (const float*)d_in[18];
    const float* Wih2         = (const float*)d_in[19];
    const float* Whh2         = (const float*)d_in[20];
    const float* bih2         = (const float*)d_in[21];
    const float* bhh2         = (const float*)d_in[22];
    const float* W_fc         = (const float*)d_in[23];
    const float* b_fc         = (const float*)d_in[24];

    float* out        = (float*)d_out;
    float* logits_out = out;
    float* alphas_out = out + B_ * NC_;
    float* betasT_out = out + B_ * NC_ + (size_t)T_ * B_ * P_;

    cudaFuncSetAttribute(stdec_kernel, cudaFuncAttributeMaxDynamicSharedMemorySize, SMEM_BYTES);
    stdec_kernel<<<NBLK, NTHR, SMEM_BYTES>>>(videos, h1, c1, h2, c2, spatialBias, temporalBias,
                                 W_h2p, b_h2p, W_sC21, b_sC21, W_h21, b_h21, W_tC21, b_tC21,
                                 Wih1, Whh1, bih1, bhh1, Wih2, Whh2, bih2, bhh2,
                                 W_fc, b_fc, logits_out, alphas_out, betasT_out);
}

// round 12
// speedup vs baseline: 1.5182x; 1.5182x over previous
#include <cuda_runtime.h>
#include <cuda_bf16.h>
#include <math.h>
#include <stdint.h>

#define B_  32
#define T_  20
#define C_  512
#define P_  196
#define H_  1024
#define NC_ 101
#define NBLK 148
#define NTHR 512
#define NWRP 16
#define KCH 128           // k elements per chunk

// SMEM byte layout: A tiles [128 m][128 k] bf16 @ stride 272 B, B tiles [32 n][128 k]
#define ASTR_B 272
#define AHI_B 0                     // 128*272 = 34816
#define ALO_B 34816
#define BHI_B 69632                 // 32*272 = 8704
#define BLO_B 78336
#define TBUF_B 87040                // per buffer
#define SMEM_BYTES (2 * TBUF_B)     // 174080

// ---------------- device scratch ----------------
__device__ float g_sA2pre[T_ * B_ * P_];
__device__ float g_tC2pre[T_ * B_ * P_];
__device__ float g_sc[B_ * P_];
__device__ float g_betaH[B_];
__device__ float g_h2n[B_ * H_];          // [b][h] fp32 (scores)
__device__ float g_h2hist[T_ * H_ * B_];  // [t][h][b]
__device__ float g_c1[H_ * B_];           // [h][b]
__device__ float g_c2[H_ * B_];
__device__ float g_beta[T_ * B_];
__device__ float g_betasT[B_ * T_];
__device__ float g_hbarN[B_ * H_];
__device__ unsigned g_cnt2[32 * 32];
__device__ volatile unsigned g_bar_gen;

// GEMM partials: [128 blocks][128 rows][32 b]
__device__ float g_part[128][128 * 32];

// bf16 hi/lo activations [b][k]
__device__ __nv_bfloat16 g_Yhi[B_ * C_], g_Ylo[B_ * C_];
__device__ __nv_bfloat16 g_h1hi[B_ * H_], g_h1lo[B_ * H_];
__device__ __nv_bfloat16 g_h2hi[B_ * H_], g_h2lo[B_ * H_];

// repacked (row-permuted, K-major) weights, hi/lo bf16
__device__ __nv_bfloat16 g_W1hi[4096 * 1536], g_W1lo[4096 * 1536];
__device__ __nv_bfloat16 g_W2hi[4096 * 2048], g_W2lo[4096 * 2048];

__device__ __forceinline__ float sigm(float x) { return 1.0f / (1.0f + __expf(-x)); }
__device__ __forceinline__ float ftanh(float x) { return 1.0f - 2.0f / (__expf(2.0f * x) + 1.0f); }
__device__ __forceinline__ float d4(float4 a, float4 b) {
    return a.x * b.x + a.y * b.y + a.z * b.z + a.w * b.w;
}

__device__ __forceinline__ void cp16(void* dst, const void* src) {
    unsigned u = (unsigned)__cvta_generic_to_shared(dst);
    asm volatile("cp.async.cg.shared.global [%0], [%1], 16;" :: "r"(u), "l"(src));
}
__device__ __forceinline__ void cp_commit() { asm volatile("cp.async.commit_group;" ::: "memory"); }
__device__ __forceinline__ void cp_wait1()  { asm volatile("cp.async.wait_group 1;" ::: "memory"); }
__device__ __forceinline__ void cp_wait0()  { asm volatile("cp.async.wait_group 0;" ::: "memory"); }

__device__ __forceinline__ uint32_t smem_u32(const void* p) {
    return (uint32_t)__cvta_generic_to_shared(p);
}

// ldmatrix x4 (b16)
__device__ __forceinline__ void ldsm4(uint32_t* r, uint32_t addr) {
    asm volatile("ldmatrix.sync.aligned.m8n8.x4.shared.b16 {%0,%1,%2,%3}, [%4];"
                 : "=r"(r[0]), "=r"(r[1]), "=r"(r[2]), "=r"(r[3]) : "r"(addr));
}
// HMMA m16n8k16 bf16 -> f32 accumulate
__device__ __forceinline__ void mma16816(float* d, const uint32_t* a, const uint32_t* b) {
    asm volatile(
        "mma.sync.aligned.m16n8k16.row.col.f32.bf16.bf16.f32 "
        "{%0,%1,%2,%3}, {%4,%5,%6,%7}, {%8,%9}, {%0,%1,%2,%3};"
        : "+f"(d[0]), "+f"(d[1]), "+f"(d[2]), "+f"(d[3])
        : "r"(a[0]), "r"(a[1]), "r"(a[2]), "r"(a[3]), "r"(b[0]), "r"(b[1]));
}

// distributed grid barrier
__device__ __forceinline__ void grid_sync(unsigned& barI, unsigned gen0) {
    barI++;
    __syncthreads();
    const int tid = threadIdx.x, bid = blockIdx.x;
    if (tid == 0) { __threadfence(); atomicAdd(&g_cnt2[(bid & 31) * 32], 1u); }
    if (bid == 0 && tid < 32) {
        unsigned nj = (tid < 20) ? 5u : 4u;
        volatile unsigned* c = &g_cnt2[tid * 32];
        while (*c < nj) __nanosleep(32);
        atomicSub(&g_cnt2[tid * 32], nj);
        __syncwarp(0xffffffffu);
        if (tid == 0) { __threadfence(); g_bar_gen = gen0 + barI; }
    } else if (tid == 0) {
        while ((unsigned)(g_bar_gen - gen0) < barI) __nanosleep(32);
    }
    __threadfence();
    __syncthreads();
}

// ---------------- LSTM GEMM phase: 128 blocks = 32 m-tiles x 4 k-slices ----------
// block: m = bid&31 (128 permuted gate-rows), ks = bid>>5 (K/4 slice).
// warp w: m-strip (w&7)*16, n-half (w>>3)*16. 3-term hi/lo split, fp32 accum.
// Writes fp32 partial tile to g_part[bid].
template <int MODE>
__device__ void lstm_gemm(const __nv_bfloat16* __restrict__ Whi,
                          const __nv_bfloat16* __restrict__ Wlo,
                          float* dsm, uint32_t smem_base) {
    constexpr int K = (MODE == 0) ? 1536 : 2048;
    constexpr int K1 = (MODE == 0) ? 512 : 1024;
    constexpr int KSL = K / 4;          // 384 or 512
    constexpr int NCH = KSL / KCH;      // 3 or 4
    const int bid = blockIdx.x, tid = threadIdx.x;
    if (bid >= 128) return;
    const int m = bid & 31, ks = bid >> 5;

    const __nv_bfloat16* X1hi = (MODE == 0) ? g_Yhi : g_h1hi;
    const __nv_bfloat16* X1lo = (MODE == 0) ? g_Ylo : g_h1lo;
    const __nv_bfloat16* X2hi = (MODE == 0) ? g_h1hi : g_h2hi;
    const __nv_bfloat16* X2lo = (MODE == 0) ? g_h1lo : g_h2lo;
    const int X1STR = (MODE == 0) ? 512 : 1024;

    char* smem_c = (char*)dsm;

    auto load_chunk = [&](int c) {
        char* basep = smem_c + (c & 1) * TBUF_B;
        const int kc = ks * KSL + c * KCH;
        // A: 2048 granules of 16B (128 rows x 16)
#pragma unroll
        for (int i = 0; i < 4; i++) {
            int g = tid + 512 * i;
            int row = g >> 4, gi = g & 15;
            size_t soff = (size_t)(m * 128 + row) * K + kc + gi * 8;
            cp16(basep + AHI_B + row * ASTR_B + gi * 16, Whi + soff);
            cp16(basep + ALO_B + row * ASTR_B + gi * 16, Wlo + soff);
        }
        // B: 512 granules (32 rows x 16)
        {
            int row = tid >> 4, gi = tid & 15;
            int k = kc + gi * 8;
            const __nv_bfloat16 *shi, *slo;
            if (k < K1) { shi = X1hi + row * X1STR + k; slo = X1lo + row * X1STR + k; }
            else        { shi = X2hi + row * 1024 + (k - K1); slo = X2lo + row * 1024 + (k - K1); }
            cp16(basep + BHI_B + row * ASTR_B + gi * 16, shi);
            cp16(basep + BLO_B + row * ASTR_B + gi * 16, slo);
        }
    };

    const int w = tid >> 5, lane = tid & 31;
    const int m0 = (w & 7) * 16, n0 = (w >> 3) * 16;
    const int mi = lane >> 3, rr = lane & 7;
    const int a_m = m0 + (mi & 1) * 8 + rr, a_k = (mi >> 1) * 8;
    const int b_n = n0 + (mi >> 1) * 8 + rr, b_k = (mi & 1) * 8;

    float acc[2][4] = {{0.f, 0.f, 0.f, 0.f}, {0.f, 0.f, 0.f, 0.f}};

    load_chunk(0); cp_commit();
    load_chunk(1); cp_commit();

    for (int c = 0; c < NCH; c++) {
        if (c + 1 < NCH) cp_wait1(); else cp_wait0();
        __syncthreads();

        uint32_t tb = smem_base + (c & 1) * TBUF_B;
        uint32_t aHi = tb + AHI_B + a_m * ASTR_B + a_k * 2;
        uint32_t aLo = tb + ALO_B + a_m * ASTR_B + a_k * 2;
        uint32_t bHi = tb + BHI_B + b_n * ASTR_B + b_k * 2;
        uint32_t bLo = tb + BLO_B + b_n * ASTR_B + b_k * 2;
#pragma unroll
        for (int kk = 0; kk < 8; kk++) {
            uint32_t ah[4], al[4], bh[4], bl[4];
            ldsm4(ah, aHi + kk * 32);
            ldsm4(al, aLo + kk * 32);
            ldsm4(bh, bHi + kk * 32);
            ldsm4(bl, bLo + kk * 32);
            mma16816(acc[0], ah, bh + 0);
            mma16816(acc[1], ah, bh + 2);
            mma16816(acc[0], ah, bl + 0);
            mma16816(acc[1], ah, bl + 2);
            mma16816(acc[0], al, bh + 0);
            mma16816(acc[1], al, bh + 2);
        }
        __syncthreads();
        if (c + 2 < NCH) { load_chunk(c + 2); cp_commit(); }
    }

    // fragments -> global partials (float2 per pair of adjacent cols)
    float* gp = g_part[bid];
    {
        int gm = lane >> 2, qc = (lane & 3) * 2;
        int r1 = m0 + gm, r2 = r1 + 8;
#pragma unroll
        for (int tt = 0; tt < 2; tt++) {
            int cc = n0 + tt * 8 + qc;
            *(float2*)&gp[r1 * 32 + cc] = make_float2(acc[tt][0], acc[tt][1]);
            *(float2*)&gp[r2 * 32 + cc] = make_float2(acc[tt][2], acc[tt][3]);
        }
    }
}

// ---------------- LSTM cell phase: all blocks, sum 4 k-slices + bias + cell ------
template <int MODE>
__device__ void lstm_cell(int t, const float* __restrict__ bih, const float* __restrict__ bhh) {
    const int bid = blockIdx.x, tid = threadIdx.x;
    for (int idx = bid * NTHR + tid; idx < H_ * B_; idx += NBLK * NTHR) {
        int ug = idx >> 5, b = idx & 31;
        int m = ug >> 5, u = ug & 31;
        float gate[4];
#pragma unroll
        for (int q = 0; q < 4; q++) {
            int row = q * 32 + u;
            float s = bih[q * 1024 + ug] + bhh[q * 1024 + ug];
#pragma unroll
            for (int ks = 0; ks < 4; ks++)
                s += g_part[ks * 32 + m][row * 32 + b];
            gate[q] = s;
        }
        float i_ = sigm(gate[0]), f_ = sigm(gate[1]), gv = ftanh(gate[2]), o_ = sigm(gate[3]);
        float* cS = (MODE == 0) ? g_c1 : g_c2;
        float cn = f_ * cS[ug * 32 + b] + i_ * gv;
        float hn = o_ * ftanh(cn);
        cS[ug * 32 + b] = cn;
        __nv_bfloat16 hhi = __float2bfloat16(hn);
        __nv_bfloat16 hlo = __float2bfloat16(hn - __bfloat162float(hhi));
        if (MODE == 0) {
            g_h1hi[b * 1024 + ug] = hhi;
            g_h1lo[b * 1024 + ug] = hlo;
        } else {
            g_h2hi[b * 1024 + ug] = hhi;
            g_h2lo[b * 1024 + ug] = hlo;
            g_h2n[b * 1024 + ug] = hn;
            g_h2hist[(size_t)t * H_ * B_ + ug * B_ + b] = hn;
        }
    }
}

// ---------------- the single persistent kernel ----------------
__global__ void __launch_bounds__(NTHR, 1)
stdec_kernel(const float* __restrict__ videos,
             const float* __restrict__ h1in, const float* __restrict__ c1in,
             const float* __restrict__ h2in, const float* __restrict__ c2in,
             const float* __restrict__ spatialBias, const float* __restrict__ temporalBias,
             const float* __restrict__ W_h2p, const float* __restrict__ b_h2p,
             const float* __restrict__ W_sC21, const float* __restrict__ b_sC21,
             const float* __restrict__ W_h21, const float* __restrict__ b_h21,
             const float* __restrict__ W_tC21, const float* __restrict__ b_tC21,
             const float* __restrict__ Wih1, const float* __restrict__ Whh1,
             const float* __restrict__ bih1, const float* __restrict__ bhh1,
             const float* __restrict__ Wih2, const float* __restrict__ Whh2,
             const float* __restrict__ bih2, const float* __restrict__ bhh2,
             const float* __restrict__ W_fc, const float* __restrict__ b_fc,
             float* __restrict__ logits_out, float* __restrict__ alphas_out,
             float* __restrict__ betasT_out) {
    extern __shared__ __align__(1024) float dsm[];
    const int bid = blockIdx.x, tid = threadIdx.x;
    const int lane = tid & 31, wid = tid >> 5;
    const int gw = bid * NWRP + wid;

    unsigned barI = 0;
    unsigned gen0 = g_bar_gen;
    uint32_t smem_base = smem_u32(dsm);

    // ---- init states ----
    for (int idx = bid * NTHR + tid; idx < B_ * H_; idx += NBLK * NTHR) {
        int b = idx >> 10, h = idx & 1023;
        float v1 = h1in[h], v2 = h2in[h];
        __nv_bfloat16 t1 = __float2bfloat16(v1);
        g_h1hi[idx] = t1; g_h1lo[idx] = __float2bfloat16(v1 - __bfloat162float(t1));
        __nv_bfloat16 t2 = __float2bfloat16(v2);
        g_h2hi[idx] = t2; g_h2lo[idx] = __float2bfloat16(v2 - __bfloat162float(t2));
        g_h2n[idx] = v2;
        g_c1[h * 32 + b] = c1in[h];
        g_c2[h * 32 + b] = c2in[h];
    }

    // ---- weight repack: permuted rows, K-major, hi/lo bf16 (once per launch) ----
    {
        const size_t N1 = (size_t)4096 * 1536, N2 = (size_t)4096 * 2048;
        for (size_t idx = (size_t)(bid * NTHR + tid); idx < N1 + N2; idx += (size_t)NBLK * NTHR) {
            if (idx < N1) {
                int R = (int)(idx / 1536), k = (int)(idx % 1536);
                int r = R & 127, mm = R >> 7;
                int q = r >> 5, u = (mm << 5) + (r & 31);
                int orig = q * 1024 + u;
                float w = (k < 512) ? Wih1[(size_t)orig * 512 + k]
                                    : Whh1[(size_t)orig * 1024 + (k - 512)];
                __nv_bfloat16 hi = __float2bfloat16(w);
                g_W1hi[idx] = hi;
                g_W1lo[idx] = __float2bfloat16(w - __bfloat162float(hi));
            } else {
                size_t j = idx - N1;
                int R = (int)(j / 2048), k = (int)(j % 2048);
                int r = R & 127, mm = R >> 7;
                int q = r >> 5, u = (mm << 5) + (r & 31);
                int orig = q * 1024 + u;
                float w = (k < 1024) ? Wih2[(size_t)orig * 1024 + k]
                                     : Whh2[(size_t)orig * 1024 + (k - 1024)];
                __nv_bfloat16 hi = __float2bfloat16(w);
                g_W2hi[j] = hi;
                g_W2lo[j] = __float2bfloat16(w - __bfloat162float(hi));
            }
        }
    }

    // ---- precompute sA2pre / tC2pre (2 tasks per block) ----
    {
        float* ws = dsm;
        float* wt = dsm + C_;
        for (int i = tid; i < C_; i += NTHR) { ws[i] = W_sC21[i]; wt[i] = W_tC21[i]; }
        __syncthreads();
        float bs0 = b_sC21[0];
        int half = tid >> 8, p = tid & 255;
        for (int task = bid * 2 + half; task < B_ * T_; task += NBLK * 2) {
            int b = task / T_, t = task % T_;
            if (p < P_) {
                const float* vp = videos + ((size_t)(b * T_ + t) * C_) * P_ + p;
                float accs = 0.f, acct = 0.f;
#pragma unroll 8
                for (int c = 0; c < C_; c++) {
                    float v = vp[(size_t)c * P_];
                    accs += v * ws[c];
                    acct += v * wt[c];
                }
                int o = (t * B_ + b) * P_ + p;
                g_sA2pre[o] = accs + bs0 + spatialBias[p];
                g_tC2pre[o] = acct;
            }
        }
        __syncthreads();
    }
    grid_sync(barI, gen0);

    // ---- recurrence: 6 phases / 6 barriers per step ----
    for (int t = 0; t < T_; t++) {
        // phase 1: scores, warp per (b,p) dot; p==196 -> betaH
        for (int task = gw; task < B_ * 197; task += NBLK * NWRP) {
            int b = task / 197, p = task % 197;
            const float4* xr = (const float4*)(g_h2n + b * H_);
            const float4* wr = (const float4*)((p < P_) ? (W_h2p + (size_t)p * H_) : W_h21);
            float acc = 0.f;
#pragma unroll
            for (int j = 0; j < 8; j++) acc += d4(wr[lane + 32 * j], xr[lane + 32 * j]);
            for (int o = 16; o; o >>= 1) acc += __shfl_xor_sync(~0u, acc, o);
            if (lane == 0) {
                if (p < P_)
                    g_sc[b * P_ + p] = acc + b_h2p[p] + g_sA2pre[(t * B_ + b) * P_ + p];
                else
                    g_betaH[b] = acc;
            }
        }
        grid_sync(barI, gen0);

        // phase 2: softmax + alpha/beta out + Y (blocks 0..127)
        if (bid < 128) {
            float* sred = dsm;
            float* s_alpha = dsm + 16;
            int b = bid >> 2, chunk = bid & 3, c0 = chunk * 128;

            float v = (tid < P_) ? g_sc[b * P_ + tid] : -1e30f;
            float m = v;
            for (int o = 16; o; o >>= 1) m = fmaxf(m, __shfl_xor_sync(~0u, m, o));
            if (lane == 0) sred[wid] = m;
            __syncthreads();
            float mAll = sred[0];
#pragma unroll
            for (int i = 1; i < NWRP; i++) mAll = fmaxf(mAll, sred[i]);
            float e = (tid < P_) ? __expf(v - mAll) : 0.f;
            float s = e;
            for (int o = 16; o; o >>= 1) s += __shfl_xor_sync(~0u, s, o);
            __syncthreads();
            if (lane == 0) sred[wid] = s;
            __syncthreads();
            float sAll = sred[0];
#pragma unroll
            for (int i = 1; i < NWRP; i++) sAll += sred[i];
            float a = e / sAll;
            __syncthreads();
            if (tid < P_) {
                s_alpha[tid] = a;
                if (chunk == 0) alphas_out[((size_t)t * B_ + b) * P_ + tid] = a;
            }
            __syncthreads();

            if (chunk == 0) {
                float acc = (tid < P_) ? a * g_tC2pre[(t * B_ + b) * P_ + tid] : 0.f;
                for (int o = 16; o; o >>= 1) acc += __shfl_xor_sync(~0u, acc, o);
                if (lane == 0) sred[wid] = acc;
                __syncthreads();
                if (tid == 0) {
                    float sum = 0.f;
#pragma unroll
                    for (int i = 0; i < NWRP; i++) sum += sred[i];
                    g_beta[t * B_ + b] = sum + g_betaH[b] + b_h21[0] + b_tC21[0] + temporalBias[0];
                }
            }

            // Y -> bf16 hi/lo [b][c]
            for (int c = wid; c < 128; c += NWRP) {
                int cg = c0 + c;
                const float* vp = videos + (((size_t)b * T_ + t) * C_ + cg) * P_;
                float acc = 0.f;
                for (int p = lane; p < P_; p += 32) acc += s_alpha[p] * vp[p];
                for (int o = 16; o; o >>= 1) acc += __shfl_xor_sync(~0u, acc, o);
                if (lane == 0) {
                    __nv_bfloat16 hy = __float2bfloat16(acc);
                    g_Yhi[b * C_ + cg] = hy;
                    g_Ylo[b * C_ + cg] = __float2bfloat16(acc - __bfloat162float(hy));
                }
            }
        }
        grid_sync(barI, gen0);

        lstm_gemm<0>(g_W1hi, g_W1lo, dsm, smem_base);
        grid_sync(barI, gen0);
        lstm_cell<0>(t, bih1, bhh1);
        grid_sync(barI, gen0);
        lstm_gemm<1>(g_W2hi, g_W2lo, dsm, smem_base);
        grid_sync(barI, gen0);
        lstm_cell<1>(t, bih2, bhh2);
        grid_sync(barI, gen0);
    }

    // ---- betas softmax over time ----
    if (bid == 0 && tid < B_) {
        int b = tid;
        float v[T_];
        float m = -1e30f;
#pragma unroll
        for (int t = 0; t < T_; t++) { v[t] = g_beta[t * B_ + b]; m = fmaxf(m, v[t]); }
        float s = 0.f;
#pragma unroll
        for (int t = 0; t < T_; t++) { v[t] = __expf(v[t] - m); s += v[t]; }
        float inv = 1.f / s;
#pragma unroll
        for (int t = 0; t < T_; t++) {
            float bt = v[t] * inv;
            g_betasT[b * T_ + t] = bt;
            betasT_out[b * T_ + t] = bt;
        }
    }
    grid_sync(barI, gen0);

    // ---- hbar[b][h] = sum_t betasT[b][t] * h2hist[t][h][b] ----
    for (int idx = bid * NTHR + tid; idx < H_ * B_; idx += NBLK * NTHR) {
        int h = idx >> 5, b = idx & 31;
        float acc = 0.f;
#pragma unroll
        for (int t = 0; t < T_; t++)
            acc += g_betasT[b * T_ + t] * g_h2hist[(size_t)t * H_ * B_ + h * B_ + b];
        g_hbarN[b * H_ + h] = acc;
    }
    grid_sync(barI, gen0);

    // ---- logits ----
    for (int task = gw; task < NC_ * B_; task += NBLK * NWRP) {
        int nc = task / B_, b = task % B_;
        const float4* wr = (const float4*)(W_fc + (size_t)nc * H_);
        const float4* xr = (const float4*)(g_hbarN + (size_t)b * H_);
        float acc = 0.f;
#pragma unroll
        for (int j = 0; j < 8; j++) acc += d4(wr[lane + 32 * j], xr[lane + 32 * j]);
        for (int o = 16; o; o >>= 1) acc += __shfl_xor_sync(~0u, acc, o);
        if (lane == 0) logits_out[b * NC_ + nc] = acc + b_fc[nc];
    }
}

// ---------------- launch ----------------
extern "C" void kernel_launch(void* const* d_in, const int* in_sizes, int n_in,
                              void* d_out, int out_size) {
    const float* videos       = (const float*)d_in[0];
    const float* h1           = (const float*)d_in[1];
    const float* c1           = (const float*)d_in[2];
    const float* h2           = (const float*)d_in[3];
    const float* c2           = (const float*)d_in[4];
    const float* spatialBias  = (const float*)d_in[5];
    const float* temporalBias = (const float*)d_in[6];
    const float* W_h2p        = (const float*)d_in[7];
    const float* b_h2p        = (const float*)d_in[8];
    const float* W_sC21       = (const float*)d_in[9];
    const float* b_sC21       = (const float*)d_in[10];
    const float* W_h21        = (const float*)d_in[11];
    const float* b_h21        = (const float*)d_in[12];
    const float* W_tC21       = (const float*)d_in[13];
    const float* b_tC21       = (const float*)d_in[14];
    const float* Wih1         = (const float*)d_in[15];
    const float* Whh1         = (const float*)d_in[16];
    const float* bih1         = (const float*)d_in[17];
    const float* bhh1         = (const float*)d_in[18];
    const float* Wih2         = (const float*)d_in[19];
    const float* Whh2         = (const float*)d_in[20];
    const float* bih2         = (const float*)d_in[21];
    const float* bhh2         = (const float*)d_in[22];
    const float* W_fc         = (const float*)d_in[23];
    const float* b_fc         = (const float*)d_in[24];

    float* out        = (float*)d_out;
    float* logits_out = out;
    float* alphas_out = out + B_ * NC_;
    float* betasT_out = out + B_ * NC_ + (size_t)T_ * B_ * P_;

    cudaFuncSetAttribute(stdec_kernel, cudaFuncAttributeMaxDynamicSharedMemorySize, SMEM_BYTES);
    stdec_kernel<<<NBLK, NTHR, SMEM_BYTES>>>(videos, h1, c1, h2, c2, spatialBias, temporalBias,
                                 W_h2p, b_h2p, W_sC21, b_sC21, W_h21, b_h21, W_tC21, b_tC21,
                                 Wih1, Whh1, bih1, bhh1, Wih2, Whh2, bih2, bhh2,
                                 W_fc, b_fc, logits_out, alphas_out, betasT_out);
}